// round 14
// baseline (speedup 1.0000x reference)
#include <cuda_runtime.h>
#include <cuda_fp16.h>
#include <cstdint>
#include <cstddef>

// ---------------- problem constants ----------------
#define TOKS 4096
#define DMODEL 512
#define NEXP 16
#define DHID 2048
#define DSH  1024
#define INV_TEMP (1.0f/0.7f)
#define LN_EPS 1e-5f
#define SHARED_SCALE 0.25f

#define BM 128
#define BN 128
#define BKH 64
#define MAX_TILES 80
#define PADMAX (MAX_TILES*BM)

#define NSTAGE 3
#define STAGE_BYTES 32768
#define SMEM_TOTAL (NSTAGE*STAGE_BYTES)
#define B_SMEM_OFF 16384

// pre1: ew1 (16384 blk) + sw1 (512 blk) + 4096 LN blocks
#define PRE1_CVT 16896
#define PRE1_BLOCKS (PRE1_CVT + TOKS)

// g1 grid: 1536 GEMM tiles, then 512 converter CTAs appended at the tail
#define G1_E_CTAS 1280
#define G1_S_CTAS 256
#define G1_TILES  (G1_E_CTAS + G1_S_CTAS)
#define G1_GRID   (G1_TILES + 512)
#define CVT2_ITERS 37          // 512 CTAs x 37 iters x 1024 elems = 19398656 elems

#define G2_E_CTAS 320
#define G2_S_CTAS 128

// ---------------- device scratch ----------------
__device__ __half g_h[TOKS*DMODEL];
__device__ float  g_mix[TOKS*DMODEL];
__device__ __half g_fh[TOKS*DMODEL];
__device__ __half g_sact[TOKS*DSH];
__device__ __half g_ffact[(size_t)TOKS*DHID];
__device__ __half g_act1[(size_t)PADMAX*DHID];
__device__ float  g_y[(size_t)PADMAX*DMODEL];
__device__ int    g_tile_e[MAX_TILES];
__device__ int    g_perm_tok[PADMAX];
__device__ int    g_top_i[TOKS*2];
__device__ float  g_top_w[TOKS*2];
__device__ int    g_apos[TOKS*2];
__device__ __half g_ew1h[(size_t)NEXP*DMODEL*DHID];
__device__ __half g_ew2h[(size_t)NEXP*DHID*DMODEL];
__device__ __half g_sw1h[(size_t)DMODEL*DSH];
__device__ __half g_sw2h[(size_t)DSH*DMODEL];
__device__ __half g_ffw1h[(size_t)DMODEL*DHID];
__device__ __half g_ffw2h[(size_t)DHID*DMODEL];

__device__ __forceinline__ float silu(float v) {
    return v * (1.0f / (1.0f + __expf(-v)));
}
__device__ __forceinline__ uint32_t smem_u32(const void* p) {
    uint32_t a;
    asm("{ .reg .u64 t; cvta.to.shared.u64 t, %1; cvt.u32.u64 %0, t; }" : "=r"(a) : "l"(p));
    return a;
}
__device__ __forceinline__ void cp16(uint32_t dst, const void* src, int sz) {
    asm volatile("cp.async.cg.shared.global [%0], [%1], 16, %2;"
        :: "r"(dst), "l"(src), "r"(sz) : "memory");
}
#define CP_COMMIT() asm volatile("cp.async.commit_group;" ::: "memory")
#define CP_WAIT1()  asm volatile("cp.async.wait_group 1;" ::: "memory")
#define LDSM_X4(r0,r1,r2,r3,addr) \
    asm volatile("ldmatrix.sync.aligned.m8n8.x4.shared.b16 {%0,%1,%2,%3}, [%4];" \
        : "=r"(r0),"=r"(r1),"=r"(r2),"=r"(r3) : "r"(addr))
#define LDSM_X4_T(r0,r1,r2,r3,addr) \
    asm volatile("ldmatrix.sync.aligned.m8n8.x4.trans.shared.b16 {%0,%1,%2,%3}, [%4];" \
        : "=r"(r0),"=r"(r1),"=r"(r2),"=r"(r3) : "r"(addr))

__device__ __forceinline__ void mma_f16(float* c, const uint32_t* a, const uint32_t* b) {
    asm volatile(
        "mma.sync.aligned.m16n8k16.row.col.f32.f16.f16.f32 "
        "{%0,%1,%2,%3}, {%4,%5,%6,%7}, {%8,%9}, {%0,%1,%2,%3};"
        : "+f"(c[0]), "+f"(c[1]), "+f"(c[2]), "+f"(c[3])
        : "r"(a[0]), "r"(a[1]), "r"(a[2]), "r"(a[3]), "r"(b[0]), "r"(b[1]));
}

// ---------------- generic GEMM body ----------------
// epi: 0 = silu -> fp16, 1 = (acc+bias)*scale -> fp32, 3 = +bias+r1+r2 -> fp32
__device__ __forceinline__ void gemm_body(
    const __half* __restrict__ A, const __half* __restrict__ Bp,
    const float* __restrict__ bp, void* __restrict__ Cv,
    int K, int N, int row0, int col0, bool gather,
    int epi, const float* __restrict__ r1, const float* __restrict__ r2,
    float scale)
{
    extern __shared__ char smem[];
    const uint32_t sbase = smem_u32(smem);
    const int tid = threadIdx.x;
    const int wid = tid >> 5, lid = tid & 31;

    uint32_t aoff[4]; uint32_t adst[4]; uint32_t amask = 0;
    uint32_t boff[4]; uint32_t bdst[4];
    #pragma unroll
    for (int i = 0; i < 4; i++) {
        int id = tid + i * 256;
        int arow = id >> 3, ac = id & 7;
        adst[i] = (uint32_t)(arow * 128 + ((ac ^ (arow & 7)) << 4));
        if (gather) {
            int t = g_perm_tok[row0 + arow];
            aoff[i] = (t >= 0) ? (uint32_t)t * (uint32_t)K + (uint32_t)(ac * 8) : 0u;
            if (t >= 0) amask |= (1u << i);
        } else {
            aoff[i] = (uint32_t)(row0 + arow) * (uint32_t)K + (uint32_t)(ac * 8);
            amask |= (1u << i);
        }
        int krow = id >> 4, bc = id & 15;
        int bcs = (bc & 8) | ((bc ^ krow) & 7);
        bdst[i] = (uint32_t)(B_SMEM_OFF + krow * 256 + (bcs << 4));
        boff[i] = (uint32_t)krow * (uint32_t)N + (uint32_t)(col0 + bc * 8);
    }
    const uint32_t bstep = (uint32_t)BKH * (uint32_t)N;

    const int wm = wid & 1;
    const int wn = wid >> 1;
    const uint32_t xorA = (uint32_t)(lid & 7);
    const uint32_t ahi  = (uint32_t)(lid >> 4);
    uint32_t abase[4];
    #pragma unroll
    for (int mt = 0; mt < 4; mt++)
        abase[mt] = (uint32_t)((wm*64 + mt*16 + (lid & 15)) * 128);
    const uint32_t browp = (uint32_t)((((lid >> 3) & 1) * 8 + (lid & 7)) * 256);
    uint32_t bcs2[2];
    #pragma unroll
    for (int pr = 0; pr < 2; pr++) {
        uint32_t c = (uint32_t)(wn*4 + pr*2) + (uint32_t)(lid >> 4);
        bcs2[pr] = ((c & 8) | ((c ^ xorA) & 7)) << 4;
    }

    float acc[4][4][4];
    #pragma unroll
    for (int mt = 0; mt < 4; mt++)
        #pragma unroll
        for (int nt = 0; nt < 4; nt++)
            #pragma unroll
            for (int u = 0; u < 4; u++) acc[mt][nt][u] = 0.0f;

    const int nst = K / BKH;

    #pragma unroll
    for (int s = 0; s < NSTAGE-1; s++) {
        uint32_t sb = sbase + s * STAGE_BYTES;
        #pragma unroll
        for (int i = 0; i < 4; i++)
            cp16(sb + adst[i], A + aoff[i] + s*BKH, (amask >> i & 1) ? 16 : 0);
        #pragma unroll
        for (int i = 0; i < 4; i++)
            cp16(sb + bdst[i], Bp + boff[i] + s*bstep, 16);
        CP_COMMIT();
    }

    int cb = 0;
    int lb = NSTAGE - 1;
    for (int c = 0; c < nst; c++) {
        CP_WAIT1();
        __syncthreads();

        int nx = c + NSTAGE - 1;
        uint32_t lbb = sbase + lb * STAGE_BYTES;
        if (nx < nst) {
            #pragma unroll
            for (int i = 0; i < 4; i++)
                cp16(lbb + adst[i], A + aoff[i] + nx*BKH, (amask >> i & 1) ? 16 : 0);
            #pragma unroll
            for (int i = 0; i < 4; i++)
                cp16(lbb + bdst[i], Bp + boff[i] + (uint32_t)nx*bstep, 16);
        }
        CP_COMMIT();

        uint32_t sb = sbase + cb * STAGE_BYTES;
        #pragma unroll
        for (int kc = 0; kc < 4; kc++) {
            uint32_t af[4][4];
            #pragma unroll
            for (int mt = 0; mt < 4; mt++) {
                uint32_t addr = sb + abase[mt] +
                    ((((uint32_t)(kc*2) + ahi) ^ xorA) << 4);
                LDSM_X4(af[mt][0], af[mt][1], af[mt][2], af[mt][3], addr);
            }
            uint32_t bf[2][4];
            #pragma unroll
            for (int pr = 0; pr < 2; pr++) {
                uint32_t addr = sb + B_SMEM_OFF + (uint32_t)(kc * 4096) + browp + bcs2[pr];
                LDSM_X4_T(bf[pr][0], bf[pr][1], bf[pr][2], bf[pr][3], addr);
            }
            #pragma unroll
            for (int mt = 0; mt < 4; mt++)
                #pragma unroll
                for (int nt = 0; nt < 4; nt++)
                    mma_f16(acc[mt][nt], af[mt], &bf[nt >> 1][(nt & 1) * 2]);
        }

        cb = (cb == NSTAGE-1) ? 0 : cb + 1;
        lb = (lb == NSTAGE-1) ? 0 : lb + 1;
    }

    const int g = lid >> 2, t = lid & 3;
    #pragma unroll
    for (int mt = 0; mt < 4; mt++) {
        int rA = row0 + wm*64 + mt*16 + g;
        #pragma unroll
        for (int nt = 0; nt < 4; nt++) {
            int cb2 = col0 + wn*32 + nt*8 + t*2;
            float bb0 = bp[cb2], bb1 = bp[cb2 + 1];
            float v0 = acc[mt][nt][0] + bb0;
            float v1 = acc[mt][nt][1] + bb1;
            float v2 = acc[mt][nt][2] + bb0;
            float v3 = acc[mt][nt][3] + bb1;
            size_t p0 = (size_t)rA * N + cb2;
            size_t p1 = (size_t)(rA + 8) * N + cb2;
            if (epi == 0) {
                __half* C = (__half*)Cv;
                *(__half2*)&C[p0] = __floats2half2_rn(silu(v0), silu(v1));
                *(__half2*)&C[p1] = __floats2half2_rn(silu(v2), silu(v3));
            } else {
                float* C = (float*)Cv;
                if (epi == 1) { v0 *= scale; v1 *= scale; v2 *= scale; v3 *= scale; }
                else {
                    v0 += r1[p0]   + r2[p0];
                    v1 += r1[p0+1] + r2[p0+1];
                    v2 += r1[p1]   + r2[p1];
                    v3 += r1[p1+1] + r2[p1+1];
                }
                *(float2*)&C[p0] = make_float2(v0, v1);
                *(float2*)&C[p1] = make_float2(v2, v3);
            }
        }
    }
}

// ---------------- g1: GEMM tiles first, converter CTAs appended at tail ----------------
__global__ void __launch_bounds__(256, 2) g1_kernel(
    const __half* __restrict__ h,
    const __half* __restrict__ ew1, const float* __restrict__ eb1, __half* __restrict__ act1,
    const __half* __restrict__ sw1, const float* __restrict__ sb1, __half* __restrict__ sact,
    const float* __restrict__ ew2, const float* __restrict__ sw2,
    const float* __restrict__ ffw1, const float* __restrict__ ffw2,
    __half* __restrict__ oew2, __half* __restrict__ osw2,
    __half* __restrict__ offw1, __half* __restrict__ offw2)
{
    int bid = blockIdx.x;
    if (bid >= G1_TILES) {
        // tail converter CTA: fills idle slots while the last GEMM wave drains
        int cid = bid - G1_TILES;
        for (int it = 0; it < CVT2_ITERS; it++) {
            size_t i = ((size_t)(cid * CVT2_ITERS + it) * 256 + threadIdx.x) * 4;
            const float* src; __half* dst; size_t off;
            if      (i < 16777216ull) { src = ew2;  dst = oew2;  off = i; }
            else if (i < 17301504ull) { src = sw2;  dst = osw2;  off = i - 16777216ull; }
            else if (i < 18350080ull) { src = ffw1; dst = offw1; off = i - 17301504ull; }
            else                      { src = ffw2; dst = offw2; off = i - 18350080ull; }
            float4 v = *(const float4*)&src[off];
            *(__half2*)&dst[off]     = __floats2half2_rn(v.x, v.y);
            *(__half2*)&dst[off + 2] = __floats2half2_rn(v.z, v.w);
        }
        return;
    }
    if (bid < G1_E_CTAS) {
        int tm = bid % MAX_TILES, tn = bid / MAX_TILES;
        int e = g_tile_e[tm];
        if (e < 0) return;
        gemm_body(h, ew1 + (size_t)e * DMODEL * DHID, eb1 + (size_t)e * DHID, act1,
                  DMODEL, DHID, tm * BM, tn * BN, true, 0, nullptr, nullptr, 1.0f);
    } else {
        int sbid = bid - G1_E_CTAS;
        int tm = sbid % 32, tn = sbid / 32;
        gemm_body(h, sw1, sb1, sact,
                  DMODEL, DSH, tm * BM, tn * BN, false, 0, nullptr, nullptr, 1.0f);
    }
}

// ---------------- merged GEMM2: expert -> y, shared -> mix ----------------
__global__ void __launch_bounds__(256, 2) g2_kernel(
    const __half* __restrict__ act1,
    const __half* __restrict__ ew2, const float* __restrict__ eb2, float* __restrict__ y,
    const __half* __restrict__ sact,
    const __half* __restrict__ sw2, const float* __restrict__ sb2, float* __restrict__ mix)
{
    int bid = blockIdx.x;
    if (bid < G2_E_CTAS) {
        int tm = bid % MAX_TILES, tn = bid / MAX_TILES;
        int e = g_tile_e[tm];
        if (e < 0) return;
        gemm_body(act1, ew2 + (size_t)e * DHID * DMODEL, eb2 + (size_t)e * DMODEL, y,
                  DHID, DMODEL, tm * BM, tn * BN, false, 1, nullptr, nullptr, 1.0f);
    } else {
        int sbid = bid - G2_E_CTAS;
        int tm = sbid % 32, tn = sbid / 32;
        gemm_body(sact, sw2, sb2, mix,
                  DSH, DMODEL, tm * BM, tn * BN, false, 1, nullptr, nullptr, SHARED_SCALE);
    }
}

// ---------------- ff GEMMs ----------------
__global__ void __launch_bounds__(256, 2) ff1_kernel(
    const __half* __restrict__ fh,
    const __half* __restrict__ ffw1, const float* __restrict__ ffb1, __half* __restrict__ ffact)
{
    int tm = blockIdx.x % 32, tn = blockIdx.x / 32;
    gemm_body(fh, ffw1, ffb1, ffact,
              DMODEL, DHID, tm * BM, tn * BN, false, 0, nullptr, nullptr, 1.0f);
}
__global__ void __launch_bounds__(256, 2) ff2_kernel(
    const __half* __restrict__ ffact,
    const __half* __restrict__ ffw2, const float* __restrict__ ffb2, float* __restrict__ out,
    const float* __restrict__ x, const float* __restrict__ mix)
{
    int tm = blockIdx.x % 32, tn = blockIdx.x / 32;
    gemm_body(ffact, ffw2, ffb2, out,
              DHID, DMODEL, tm * BM, tn * BN, false, 3, x, mix, 1.0f);
}

// ---------------- pre1: ew1+sw1 conversion + input LN + router ----------------
__global__ void __launch_bounds__(256) pre1_kernel(
    const float* __restrict__ ew1, const float* __restrict__ sw1,
    __half* __restrict__ oew1, __half* __restrict__ osw1,
    const float* __restrict__ x,
    const float* __restrict__ gamma, const float* __restrict__ beta,
    const float* __restrict__ rw, const float* __restrict__ rb,
    __half* __restrict__ hout)
{
    int bid = blockIdx.x, tid = threadIdx.x;
    if (bid < PRE1_CVT) {
        size_t i = ((size_t)bid * 256 + tid) * 4;
        const float* src; __half* dst; size_t off;
        if (i < 16777216ull) { src = ew1; dst = oew1; off = i; }
        else                 { src = sw1; dst = osw1; off = i - 16777216ull; }
        float4 v = *(const float4*)&src[off];
        *(__half2*)&dst[off]     = __floats2half2_rn(v.x, v.y);
        *(__half2*)&dst[off + 2] = __floats2half2_rn(v.z, v.w);
        return;
    }

    int tok = bid - PRE1_CVT;
    __shared__ float hs[DMODEL];
    __shared__ float red[2][8];
    __shared__ float logits[NEXP];
    int wid = tid >> 5;

    int d = tid * 2;
    float2 v = *(const float2*)&x[(size_t)tok*DMODEL + d];
    float s = v.x + v.y;
    float q = v.x*v.x + v.y*v.y;
    #pragma unroll
    for (int o = 16; o; o >>= 1) {
        s += __shfl_xor_sync(0xffffffffu, s, o);
        q += __shfl_xor_sync(0xffffffffu, q, o);
    }
    if ((tid & 31) == 0) { red[0][wid] = s; red[1][wid] = q; }
    __syncthreads();
    s = 0.0f; q = 0.0f;
    #pragma unroll
    for (int i = 0; i < 8; i++) { s += red[0][i]; q += red[1][i]; }
    float mu  = s * (1.0f/DMODEL);
    float var = q * (1.0f/DMODEL) - mu*mu;
    float rs  = rsqrtf(var + LN_EPS);

    float a0 = (v.x-mu)*rs*gamma[d+0] + beta[d+0];
    float a1 = (v.y-mu)*rs*gamma[d+1] + beta[d+1];
    *(__half2*)&hout[(size_t)tok*DMODEL + d] = __floats2half2_rn(a0, a1);
    hs[d+0] = a0; hs[d+1] = a1;
    __syncthreads();

    if (tid < NEXP) {
        float acc = 0.0f;
        #pragma unroll 8
        for (int dd = 0; dd < DMODEL; dd++) acc += hs[dd] * rw[dd*NEXP + tid];
        logits[tid] = (acc + rb[tid]) * INV_TEMP;
    }
    __syncthreads();
    if (tid == 0) {
        float m = logits[0];
        #pragma unroll
        for (int e = 1; e < NEXP; e++) m = fmaxf(m, logits[e]);
        float pp[NEXP]; float sum = 0.0f;
        #pragma unroll
        for (int e = 0; e < NEXP; e++) { pp[e] = __expf(logits[e]-m); sum += pp[e]; }
        float inv = 1.0f / sum;
        int i0 = 0; float b0 = pp[0];
        #pragma unroll
        for (int e = 1; e < NEXP; e++) if (pp[e] > b0) { b0 = pp[e]; i0 = e; }
        int i1 = -1; float b1 = -1.0f;
        #pragma unroll
        for (int e = 0; e < NEXP; e++) if (e != i0 && pp[e] > b1) { b1 = pp[e]; i1 = e; }
        g_top_i[tok*2+0] = i0; g_top_i[tok*2+1] = i1;
        g_top_w[tok*2+0] = b0*inv; g_top_w[tok*2+1] = b1*inv;
    }
}

// ---------------- combine + final-FF LayerNorm ----------------
__global__ void __launch_bounds__(128) ln2_kernel(
    float* __restrict__ xw,
    const float* __restrict__ gamma, const float* __restrict__ beta,
    __half* __restrict__ out)
{
    int tok = blockIdx.x, tid = threadIdx.x;
    __shared__ float red[2][4];

    int d = tid*4;
    float4 v = *(const float4*)&xw[(size_t)tok*DMODEL + d];
    int g0 = g_apos[tok*2+0], g1 = g_apos[tok*2+1];
    float w0 = g_top_w[tok*2+0], w1 = g_top_w[tok*2+1];
    float4 a = *(const float4*)&g_y[(size_t)g0*DMODEL + d];
    float4 b = *(const float4*)&g_y[(size_t)g1*DMODEL + d];
    v.x += w0*a.x + w1*b.x;
    v.y += w0*a.y + w1*b.y;
    v.z += w0*a.z + w1*b.z;
    v.w += w0*a.w + w1*b.w;
    *(float4*)&xw[(size_t)tok*DMODEL + d] = v;

    float s = v.x+v.y+v.z+v.w;
    float q = v.x*v.x+v.y*v.y+v.z*v.z+v.w*v.w;
    #pragma unroll
    for (int o = 16; o; o >>= 1) {
        s += __shfl_xor_sync(0xffffffffu, s, o);
        q += __shfl_xor_sync(0xffffffffu, q, o);
    }
    if ((tid & 31) == 0) { red[0][tid>>5] = s; red[1][tid>>5] = q; }
    __syncthreads();
    s = red[0][0]+red[0][1]+red[0][2]+red[0][3];
    q = red[1][0]+red[1][1]+red[1][2]+red[1][3];
    float mu  = s * (1.0f/DMODEL);
    float var = q * (1.0f/DMODEL) - mu*mu;
    float rs  = rsqrtf(var + LN_EPS);

    float o0 = (v.x-mu)*rs*gamma[d+0] + beta[d+0];
    float o1 = (v.y-mu)*rs*gamma[d+1] + beta[d+1];
    float o2 = (v.z-mu)*rs*gamma[d+2] + beta[d+2];
    float o3 = (v.w-mu)*rs*gamma[d+3] + beta[d+3];
    *(__half2*)&out[(size_t)tok*DMODEL + d]     = __floats2half2_rn(o0, o1);
    *(__half2*)&out[(size_t)tok*DMODEL + d + 2] = __floats2half2_rn(o2, o3);
}

// ---------------- fused setup + scatter (single block) ----------------
__global__ void __launch_bounds__(256) setup_scatter_kernel() {
    __shared__ int scnt[NEXP];
    __shared__ int soff[NEXP];
    __shared__ int sfill[NEXP];
    int tid = threadIdx.x;

    if (tid < NEXP) { scnt[tid] = 0; sfill[tid] = 0; }
    for (int i = tid; i < PADMAX; i += 256) g_perm_tok[i] = -1;
    if (tid < MAX_TILES) g_tile_e[tid] = -1;
    __syncthreads();

    for (int i = tid; i < TOKS*2; i += 256)
        atomicAdd(&scnt[g_top_i[i]], 1);
    __syncthreads();

    if (tid == 0) {
        int running = 0;
        for (int e = 0; e < NEXP; e++) {
            soff[e] = running;
            int nt = (scnt[e] + BM - 1) / BM;
            int t0 = running / BM;
            for (int t = 0; t < nt; t++) g_tile_e[t0 + t] = e;
            running += nt * BM;
        }
    }
    __syncthreads();

    for (int i = tid; i < TOKS*2; i += 256) {
        int e = g_top_i[i];
        int pos = atomicAdd(&sfill[e], 1);
        int gp = soff[e] + pos;
        g_perm_tok[gp] = i >> 1;
        g_apos[i] = gp;
    }
}

// ---------------- launcher (single stream, zero resource creation) ----------------
extern "C" void kernel_launch(void* const* d_in, const int* in_sizes, int n_in,
                              void* d_out, int out_size)
{
    const float* x      = (const float*)d_in[0];
    const float* ln_g   = (const float*)d_in[1];
    const float* ln_b   = (const float*)d_in[2];
    const float* rw     = (const float*)d_in[3];
    const float* rb     = (const float*)d_in[4];
    const float* ew1    = (const float*)d_in[5];
    const float* eb1    = (const float*)d_in[6];
    const float* ew2    = (const float*)d_in[7];
    const float* eb2    = (const float*)d_in[8];
    const float* sw1    = (const float*)d_in[9];
    const float* sb1    = (const float*)d_in[10];
    const float* sw2    = (const float*)d_in[11];
    const float* sb2    = (const float*)d_in[12];
    const float* ffln_g = (const float*)d_in[13];
    const float* ffln_b = (const float*)d_in[14];
    const float* ffw1   = (const float*)d_in[15];
    const float* ffb1   = (const float*)d_in[16];
    const float* ffw2   = (const float*)d_in[17];
    const float* ffb2   = (const float*)d_in[18];
    float* out = (float*)d_out;

    void* p;
    cudaGetSymbolAddress(&p, g_h);     __half* ph     = (__half*)p;
    cudaGetSymbolAddress(&p, g_mix);   float*  pmix   = (float*)p;
    cudaGetSymbolAddress(&p, g_fh);    __half* pfh    = (__half*)p;
    cudaGetSymbolAddress(&p, g_sact);  __half* psact  = (__half*)p;
    cudaGetSymbolAddress(&p, g_ffact); __half* pffact = (__half*)p;
    cudaGetSymbolAddress(&p, g_act1);  __half* pact1  = (__half*)p;
    cudaGetSymbolAddress(&p, g_y);     float*  py     = (float*)p;
    cudaGetSymbolAddress(&p, g_ew1h);  __half* pew1h  = (__half*)p;
    cudaGetSymbolAddress(&p, g_ew2h);  __half* pew2h  = (__half*)p;
    cudaGetSymbolAddress(&p, g_sw1h);  __half* psw1h  = (__half*)p;
    cudaGetSymbolAddress(&p, g_sw2h);  __half* psw2h  = (__half*)p;
    cudaGetSymbolAddress(&p, g_ffw1h); __half* pffw1h = (__half*)p;
    cudaGetSymbolAddress(&p, g_ffw2h); __half* pffw2h = (__half*)p;

    cudaFuncSetAttribute(g1_kernel,  cudaFuncAttributeMaxDynamicSharedMemorySize, SMEM_TOTAL);
    cudaFuncSetAttribute(g2_kernel,  cudaFuncAttributeMaxDynamicSharedMemorySize, SMEM_TOTAL);
    cudaFuncSetAttribute(ff1_kernel, cudaFuncAttributeMaxDynamicSharedMemorySize, SMEM_TOTAL);
    cudaFuncSetAttribute(ff2_kernel, cudaFuncAttributeMaxDynamicSharedMemorySize, SMEM_TOTAL);

    // 1. ew1+sw1 conversion + input LN + router (one launch)
    pre1_kernel<<<PRE1_BLOCKS, 256>>>(ew1, sw1, pew1h, psw1h,
                                      x, ln_g, ln_b, rw, rb, ph);
    // 2. counts + offsets + tile map + scatter
    setup_scatter_kernel<<<1, 256>>>();
    // 3. g1 GEMM tiles + tail-appended cvt2 CTAs (fill drain slots with HBM work)
    g1_kernel<<<G1_GRID, 256, SMEM_TOTAL>>>(
        ph, pew1h, eb1, pact1, psw1h, sb1, psact,
        ew2, sw2, ffw1, ffw2, pew2h, psw2h, pffw1h, pffw2h);
    // 4. merged GEMM2 (weights converted inside g1 launch)
    g2_kernel<<<G2_E_CTAS + G2_S_CTAS, 256, SMEM_TOTAL>>>(
        pact1, pew2h, eb2, py, psact, psw2h, sb2, pmix);
    // 5. combine(top-2) + final-FF LayerNorm
    ln2_kernel<<<TOKS, 128>>>(pmix, ffln_g, ffln_b, pfh);
    // 6. FF GEMM1 + SiLU
    ff1_kernel<<<512, 256, SMEM_TOTAL>>>(pfh, pffw1h, ffb1, pffact);
    // 7. FF GEMM2 + x + moe_out -> out
    ff2_kernel<<<128, 256, SMEM_TOTAL>>>(pffact, pffw2h, ffb2, out, x, pmix);
}

// round 16
// speedup vs baseline: 1.1007x; 1.1007x over previous
#include <cuda_runtime.h>
#include <cuda_fp16.h>
#include <cstdint>
#include <cstddef>

// ---------------- problem constants ----------------
#define TOKS 4096
#define DMODEL 512
#define NEXP 16
#define DHID 2048
#define DSH  1024
#define INV_TEMP (1.0f/0.7f)
#define LN_EPS 1e-5f
#define SHARED_SCALE 0.25f

#define BM 128
#define BN 128
#define BKH 64
#define MAX_TILES 80
#define PADMAX (MAX_TILES*BM)

#define NSTAGE 3
#define STAGE_BYTES 32768
#define SMEM_TOTAL (NSTAGE*STAGE_BYTES)
#define B_SMEM_OFF 16384

// fused cvt: 36700160 elems / 2048 per block = 17920 blocks, then 4096 LN blocks
#define CVT_BLOCKS 17920
#define PRE_BLOCKS (CVT_BLOCKS + TOKS)

#define G1_E_CTAS 1280
#define G1_S_CTAS 256
#define G2_E_CTAS 320
#define G2_S_CTAS 128

// ---------------- device scratch ----------------
__device__ __half g_h[TOKS*DMODEL];
__device__ float  g_mix[TOKS*DMODEL];
__device__ __half g_fh[TOKS*DMODEL];
__device__ __half g_sact[TOKS*DSH];
__device__ __half g_ffact[(size_t)TOKS*DHID];
__device__ __half g_act1[(size_t)PADMAX*DHID];
__device__ float  g_y[(size_t)PADMAX*DMODEL];
__device__ int    g_tile_e[MAX_TILES];
__device__ int    g_perm_tok[PADMAX];
__device__ int    g_top_i[TOKS*2];
__device__ float  g_top_w[TOKS*2];
__device__ int    g_apos[TOKS*2];
__device__ __half g_ew1h[(size_t)NEXP*DMODEL*DHID];
__device__ __half g_ew2h[(size_t)NEXP*DHID*DMODEL];
__device__ __half g_sw1h[(size_t)DMODEL*DSH];
__device__ __half g_sw2h[(size_t)DSH*DMODEL];
__device__ __half g_ffw1h[(size_t)DMODEL*DHID];
__device__ __half g_ffw2h[(size_t)DHID*DMODEL];

__device__ __forceinline__ float silu(float v) {
    return v * (1.0f / (1.0f + __expf(-v)));
}
__device__ __forceinline__ uint32_t smem_u32(const void* p) {
    uint32_t a;
    asm("{ .reg .u64 t; cvta.to.shared.u64 t, %1; cvt.u32.u64 %0, t; }" : "=r"(a) : "l"(p));
    return a;
}
__device__ __forceinline__ void cp16(uint32_t dst, const void* src, int sz) {
    asm volatile("cp.async.cg.shared.global [%0], [%1], 16, %2;"
        :: "r"(dst), "l"(src), "r"(sz) : "memory");
}
#define CP_COMMIT() asm volatile("cp.async.commit_group;" ::: "memory")
#define CP_WAIT1()  asm volatile("cp.async.wait_group 1;" ::: "memory")
#define LDSM_X4(r0,r1,r2,r3,addr) \
    asm volatile("ldmatrix.sync.aligned.m8n8.x4.shared.b16 {%0,%1,%2,%3}, [%4];" \
        : "=r"(r0),"=r"(r1),"=r"(r2),"=r"(r3) : "r"(addr))
#define LDSM_X4_T(r0,r1,r2,r3,addr) \
    asm volatile("ldmatrix.sync.aligned.m8n8.x4.trans.shared.b16 {%0,%1,%2,%3}, [%4];" \
        : "=r"(r0),"=r"(r1),"=r"(r2),"=r"(r3) : "r"(addr))

__device__ __forceinline__ void mma_f16(float* c, const uint32_t* a, const uint32_t* b) {
    asm volatile(
        "mma.sync.aligned.m16n8k16.row.col.f32.f16.f16.f32 "
        "{%0,%1,%2,%3}, {%4,%5,%6,%7}, {%8,%9}, {%0,%1,%2,%3};"
        : "+f"(c[0]), "+f"(c[1]), "+f"(c[2]), "+f"(c[3])
        : "r"(a[0]), "r"(a[1]), "r"(a[2]), "r"(a[3]), "r"(b[0]), "r"(b[1]));
}

// ---------------- generic GEMM body ----------------
// epi: 0 = silu -> fp16, 1 = (acc+bias)*scale -> fp32, 3 = +bias+r1+r2 -> fp32
__device__ __forceinline__ void gemm_body(
    const __half* __restrict__ A, const __half* __restrict__ Bp,
    const float* __restrict__ bp, void* __restrict__ Cv,
    int K, int N, int row0, int col0, bool gather,
    int epi, const float* __restrict__ r1, const float* __restrict__ r2,
    float scale)
{
    extern __shared__ char smem[];
    const uint32_t sbase = smem_u32(smem);
    const int tid = threadIdx.x;
    const int wid = tid >> 5, lid = tid & 31;

    uint32_t aoff[4]; uint32_t adst[4]; uint32_t amask = 0;
    uint32_t boff[4]; uint32_t bdst[4];
    #pragma unroll
    for (int i = 0; i < 4; i++) {
        int id = tid + i * 256;
        int arow = id >> 3, ac = id & 7;
        adst[i] = (uint32_t)(arow * 128 + ((ac ^ (arow & 7)) << 4));
        if (gather) {
            int t = g_perm_tok[row0 + arow];
            aoff[i] = (t >= 0) ? (uint32_t)t * (uint32_t)K + (uint32_t)(ac * 8) : 0u;
            if (t >= 0) amask |= (1u << i);
        } else {
            aoff[i] = (uint32_t)(row0 + arow) * (uint32_t)K + (uint32_t)(ac * 8);
            amask |= (1u << i);
        }
        int krow = id >> 4, bc = id & 15;
        int bcs = (bc & 8) | ((bc ^ krow) & 7);
        bdst[i] = (uint32_t)(B_SMEM_OFF + krow * 256 + (bcs << 4));
        boff[i] = (uint32_t)krow * (uint32_t)N + (uint32_t)(col0 + bc * 8);
    }
    const uint32_t bstep = (uint32_t)BKH * (uint32_t)N;

    const int wm = wid & 1;
    const int wn = wid >> 1;
    const uint32_t xorA = (uint32_t)(lid & 7);
    const uint32_t ahi  = (uint32_t)(lid >> 4);
    uint32_t abase[4];
    #pragma unroll
    for (int mt = 0; mt < 4; mt++)
        abase[mt] = (uint32_t)((wm*64 + mt*16 + (lid & 15)) * 128);
    const uint32_t browp = (uint32_t)((((lid >> 3) & 1) * 8 + (lid & 7)) * 256);
    uint32_t bcs2[2];
    #pragma unroll
    for (int pr = 0; pr < 2; pr++) {
        uint32_t c = (uint32_t)(wn*4 + pr*2) + (uint32_t)(lid >> 4);
        bcs2[pr] = ((c & 8) | ((c ^ xorA) & 7)) << 4;
    }

    float acc[4][4][4];
    #pragma unroll
    for (int mt = 0; mt < 4; mt++)
        #pragma unroll
        for (int nt = 0; nt < 4; nt++)
            #pragma unroll
            for (int u = 0; u < 4; u++) acc[mt][nt][u] = 0.0f;

    const int nst = K / BKH;

    #pragma unroll
    for (int s = 0; s < NSTAGE-1; s++) {
        uint32_t sb = sbase + s * STAGE_BYTES;
        #pragma unroll
        for (int i = 0; i < 4; i++)
            cp16(sb + adst[i], A + aoff[i] + s*BKH, (amask >> i & 1) ? 16 : 0);
        #pragma unroll
        for (int i = 0; i < 4; i++)
            cp16(sb + bdst[i], Bp + boff[i] + s*bstep, 16);
        CP_COMMIT();
    }

    int cb = 0;
    int lb = NSTAGE - 1;
    for (int c = 0; c < nst; c++) {
        CP_WAIT1();
        __syncthreads();

        int nx = c + NSTAGE - 1;
        uint32_t lbb = sbase + lb * STAGE_BYTES;
        if (nx < nst) {
            #pragma unroll
            for (int i = 0; i < 4; i++)
                cp16(lbb + adst[i], A + aoff[i] + nx*BKH, (amask >> i & 1) ? 16 : 0);
            #pragma unroll
            for (int i = 0; i < 4; i++)
                cp16(lbb + bdst[i], Bp + boff[i] + (uint32_t)nx*bstep, 16);
        }
        CP_COMMIT();

        uint32_t sb = sbase + cb * STAGE_BYTES;
        #pragma unroll
        for (int kc = 0; kc < 4; kc++) {
            uint32_t af[4][4];
            #pragma unroll
            for (int mt = 0; mt < 4; mt++) {
                uint32_t addr = sb + abase[mt] +
                    ((((uint32_t)(kc*2) + ahi) ^ xorA) << 4);
                LDSM_X4(af[mt][0], af[mt][1], af[mt][2], af[mt][3], addr);
            }
            uint32_t bf[2][4];
            #pragma unroll
            for (int pr = 0; pr < 2; pr++) {
                uint32_t addr = sb + B_SMEM_OFF + (uint32_t)(kc * 4096) + browp + bcs2[pr];
                LDSM_X4_T(bf[pr][0], bf[pr][1], bf[pr][2], bf[pr][3], addr);
            }
            #pragma unroll
            for (int mt = 0; mt < 4; mt++)
                #pragma unroll
                for (int nt = 0; nt < 4; nt++)
                    mma_f16(acc[mt][nt], af[mt], &bf[nt >> 1][(nt & 1) * 2]);
        }

        cb = (cb == NSTAGE-1) ? 0 : cb + 1;
        lb = (lb == NSTAGE-1) ? 0 : lb + 1;
    }

    const int g = lid >> 2, t = lid & 3;
    #pragma unroll
    for (int mt = 0; mt < 4; mt++) {
        int rA = row0 + wm*64 + mt*16 + g;
        #pragma unroll
        for (int nt = 0; nt < 4; nt++) {
            int cb2 = col0 + wn*32 + nt*8 + t*2;
            float bb0 = bp[cb2], bb1 = bp[cb2 + 1];
            float v0 = acc[mt][nt][0] + bb0;
            float v1 = acc[mt][nt][1] + bb1;
            float v2 = acc[mt][nt][2] + bb0;
            float v3 = acc[mt][nt][3] + bb1;
            size_t p0 = (size_t)rA * N + cb2;
            size_t p1 = (size_t)(rA + 8) * N + cb2;
            if (epi == 0) {
                __half* C = (__half*)Cv;
                *(__half2*)&C[p0] = __floats2half2_rn(silu(v0), silu(v1));
                *(__half2*)&C[p1] = __floats2half2_rn(silu(v2), silu(v3));
            } else {
                float* C = (float*)Cv;
                if (epi == 1) { v0 *= scale; v1 *= scale; v2 *= scale; v3 *= scale; }
                else {
                    v0 += r1[p0]   + r2[p0];
                    v1 += r1[p0+1] + r2[p0+1];
                    v2 += r1[p1]   + r2[p1];
                    v3 += r1[p1+1] + r2[p1+1];
                }
                *(float2*)&C[p0] = make_float2(v0, v1);
                *(float2*)&C[p1] = make_float2(v2, v3);
            }
        }
    }
}

// ---------------- merged GEMM1: expert (gathered) + shared ----------------
__global__ void __launch_bounds__(256, 2) g1_kernel(
    const __half* __restrict__ h,
    const __half* __restrict__ ew1, const float* __restrict__ eb1, __half* __restrict__ act1,
    const __half* __restrict__ sw1, const float* __restrict__ sb1, __half* __restrict__ sact)
{
    int bid = blockIdx.x;
    if (bid < G1_E_CTAS) {
        int tm = bid % MAX_TILES, tn = bid / MAX_TILES;
        int e = g_tile_e[tm];
        if (e < 0) return;
        gemm_body(h, ew1 + (size_t)e * DMODEL * DHID, eb1 + (size_t)e * DHID, act1,
                  DMODEL, DHID, tm * BM, tn * BN, true, 0, nullptr, nullptr, 1.0f);
    } else {
        int sbid = bid - G1_E_CTAS;
        int tm = sbid % 32, tn = sbid / 32;
        gemm_body(h, sw1, sb1, sact,
                  DMODEL, DSH, tm * BM, tn * BN, false, 0, nullptr, nullptr, 1.0f);
    }
}

// ---------------- merged GEMM2: expert -> y, shared -> mix ----------------
__global__ void __launch_bounds__(256, 2) g2_kernel(
    const __half* __restrict__ act1,
    const __half* __restrict__ ew2, const float* __restrict__ eb2, float* __restrict__ y,
    const __half* __restrict__ sact,
    const __half* __restrict__ sw2, const float* __restrict__ sb2, float* __restrict__ mix)
{
    int bid = blockIdx.x;
    if (bid < G2_E_CTAS) {
        int tm = bid % MAX_TILES, tn = bid / MAX_TILES;
        int e = g_tile_e[tm];
        if (e < 0) return;
        gemm_body(act1, ew2 + (size_t)e * DHID * DMODEL, eb2 + (size_t)e * DMODEL, y,
                  DHID, DMODEL, tm * BM, tn * BN, false, 1, nullptr, nullptr, 1.0f);
    } else {
        int sbid = bid - G2_E_CTAS;
        int tm = sbid % 32, tn = sbid / 32;
        gemm_body(sact, sw2, sb2, mix,
                  DSH, DMODEL, tm * BM, tn * BN, false, 1, nullptr, nullptr, SHARED_SCALE);
    }
}

// ---------------- ff GEMMs ----------------
__global__ void __launch_bounds__(256, 2) ff1_kernel(
    const __half* __restrict__ fh,
    const __half* __restrict__ ffw1, const float* __restrict__ ffb1, __half* __restrict__ ffact)
{
    int tm = blockIdx.x % 32, tn = blockIdx.x / 32;
    gemm_body(fh, ffw1, ffb1, ffact,
              DMODEL, DHID, tm * BM, tn * BN, false, 0, nullptr, nullptr, 1.0f);
}
__global__ void __launch_bounds__(256, 2) ff2_kernel(
    const __half* __restrict__ ffact,
    const __half* __restrict__ ffw2, const float* __restrict__ ffb2, float* __restrict__ out,
    const float* __restrict__ x, const float* __restrict__ mix)
{
    int tm = blockIdx.x % 32, tn = blockIdx.x / 32;
    gemm_body(ffact, ffw2, ffb2, out,
              DHID, DMODEL, tm * BM, tn * BN, false, 3, x, mix, 1.0f);
}

// ---------------- fused: wide weight conversion (8 elems/thread) + LN + router ----------------
// cvt blocks cover 2048 elems each; segment boundaries (in blocks):
// ew1 [0,8192) | ew2 [8192,16384) | sw1 [16384,16640) | sw2 [16640,16896)
// ffw1 [16896,17408) | ffw2 [17408,17920)
__global__ void __launch_bounds__(256) pre_kernel(
    const float* __restrict__ ew1, const float* __restrict__ ew2,
    const float* __restrict__ sw1, const float* __restrict__ sw2,
    const float* __restrict__ ffw1, const float* __restrict__ ffw2,
    __half* __restrict__ oew1, __half* __restrict__ oew2,
    __half* __restrict__ osw1, __half* __restrict__ osw2,
    __half* __restrict__ offw1, __half* __restrict__ offw2,
    const float* __restrict__ x,
    const float* __restrict__ gamma, const float* __restrict__ beta,
    const float* __restrict__ rw, const float* __restrict__ rb,
    __half* __restrict__ hout)
{
    int bid = blockIdx.x, tid = threadIdx.x;
    if (bid < CVT_BLOCKS) {
        const float* src; __half* dst; int b;
        if      (bid < 8192)  { src = ew1;  dst = oew1;  b = bid; }
        else if (bid < 16384) { src = ew2;  dst = oew2;  b = bid - 8192; }
        else if (bid < 16640) { src = sw1;  dst = osw1;  b = bid - 16384; }
        else if (bid < 16896) { src = sw2;  dst = osw2;  b = bid - 16640; }
        else if (bid < 17408) { src = ffw1; dst = offw1; b = bid - 16896; }
        else                  { src = ffw2; dst = offw2; b = bid - 17408; }
        size_t off = ((size_t)b * 256 + tid) * 8;
        float4 v0 = *(const float4*)&src[off];
        float4 v1 = *(const float4*)&src[off + 4];
        __half2 h0 = __floats2half2_rn(v0.x, v0.y);
        __half2 h1 = __floats2half2_rn(v0.z, v0.w);
        __half2 h2 = __floats2half2_rn(v1.x, v1.y);
        __half2 h3 = __floats2half2_rn(v1.z, v1.w);
        uint4 o;
        o.x = *(uint32_t*)&h0;
        o.y = *(uint32_t*)&h1;
        o.z = *(uint32_t*)&h2;
        o.w = *(uint32_t*)&h3;
        *(uint4*)&dst[off] = o;
        return;
    }

    // ---- LayerNorm + router (256 threads, 2 floats each) ----
    int tok = bid - CVT_BLOCKS;
    __shared__ float hs[DMODEL];
    __shared__ float red[2][8];
    __shared__ float logits[NEXP];
    int wid = tid >> 5;

    int d = tid * 2;
    float2 v = *(const float2*)&x[(size_t)tok*DMODEL + d];
    float s = v.x + v.y;
    float q = v.x*v.x + v.y*v.y;
    #pragma unroll
    for (int o = 16; o; o >>= 1) {
        s += __shfl_xor_sync(0xffffffffu, s, o);
        q += __shfl_xor_sync(0xffffffffu, q, o);
    }
    if ((tid & 31) == 0) { red[0][wid] = s; red[1][wid] = q; }
    __syncthreads();
    s = 0.0f; q = 0.0f;
    #pragma unroll
    for (int i = 0; i < 8; i++) { s += red[0][i]; q += red[1][i]; }
    float mu  = s * (1.0f/DMODEL);
    float var = q * (1.0f/DMODEL) - mu*mu;
    float rs  = rsqrtf(var + LN_EPS);

    float a0 = (v.x-mu)*rs*gamma[d+0] + beta[d+0];
    float a1 = (v.y-mu)*rs*gamma[d+1] + beta[d+1];
    *(__half2*)&hout[(size_t)tok*DMODEL + d] = __floats2half2_rn(a0, a1);
    hs[d+0] = a0; hs[d+1] = a1;
    __syncthreads();

    if (tid < NEXP) {
        float acc = 0.0f;
        #pragma unroll 8
        for (int dd = 0; dd < DMODEL; dd++) acc += hs[dd] * rw[dd*NEXP + tid];
        logits[tid] = (acc + rb[tid]) * INV_TEMP;
    }
    __syncthreads();
    if (tid == 0) {
        float m = logits[0];
        #pragma unroll
        for (int e = 1; e < NEXP; e++) m = fmaxf(m, logits[e]);
        float pp[NEXP]; float sum = 0.0f;
        #pragma unroll
        for (int e = 0; e < NEXP; e++) { pp[e] = __expf(logits[e]-m); sum += pp[e]; }
        float inv = 1.0f / sum;
        int i0 = 0; float b0 = pp[0];
        #pragma unroll
        for (int e = 1; e < NEXP; e++) if (pp[e] > b0) { b0 = pp[e]; i0 = e; }
        int i1 = -1; float b1 = -1.0f;
        #pragma unroll
        for (int e = 0; e < NEXP; e++) if (e != i0 && pp[e] > b1) { b1 = pp[e]; i1 = e; }
        g_top_i[tok*2+0] = i0; g_top_i[tok*2+1] = i1;
        g_top_w[tok*2+0] = b0*inv; g_top_w[tok*2+1] = b1*inv;
    }
}

// ---------------- combine + final-FF LayerNorm ----------------
__global__ void __launch_bounds__(128) ln2_kernel(
    float* __restrict__ xw,
    const float* __restrict__ gamma, const float* __restrict__ beta,
    __half* __restrict__ out)
{
    int tok = blockIdx.x, tid = threadIdx.x;
    __shared__ float red[2][4];

    int d = tid*4;
    float4 v = *(const float4*)&xw[(size_t)tok*DMODEL + d];
    int g0 = g_apos[tok*2+0], g1 = g_apos[tok*2+1];
    float w0 = g_top_w[tok*2+0], w1 = g_top_w[tok*2+1];
    float4 a = *(const float4*)&g_y[(size_t)g0*DMODEL + d];
    float4 b = *(const float4*)&g_y[(size_t)g1*DMODEL + d];
    v.x += w0*a.x + w1*b.x;
    v.y += w0*a.y + w1*b.y;
    v.z += w0*a.z + w1*b.z;
    v.w += w0*a.w + w1*b.w;
    *(float4*)&xw[(size_t)tok*DMODEL + d] = v;

    float s = v.x+v.y+v.z+v.w;
    float q = v.x*v.x+v.y*v.y+v.z*v.z+v.w*v.w;
    #pragma unroll
    for (int o = 16; o; o >>= 1) {
        s += __shfl_xor_sync(0xffffffffu, s, o);
        q += __shfl_xor_sync(0xffffffffu, q, o);
    }
    if ((tid & 31) == 0) { red[0][tid>>5] = s; red[1][tid>>5] = q; }
    __syncthreads();
    s = red[0][0]+red[0][1]+red[0][2]+red[0][3];
    q = red[1][0]+red[1][1]+red[1][2]+red[1][3];
    float mu  = s * (1.0f/DMODEL);
    float var = q * (1.0f/DMODEL) - mu*mu;
    float rs  = rsqrtf(var + LN_EPS);

    float o0 = (v.x-mu)*rs*gamma[d+0] + beta[d+0];
    float o1 = (v.y-mu)*rs*gamma[d+1] + beta[d+1];
    float o2 = (v.z-mu)*rs*gamma[d+2] + beta[d+2];
    float o3 = (v.w-mu)*rs*gamma[d+3] + beta[d+3];
    *(__half2*)&out[(size_t)tok*DMODEL + d]     = __floats2half2_rn(o0, o1);
    *(__half2*)&out[(size_t)tok*DMODEL + d + 2] = __floats2half2_rn(o2, o3);
}

// ---------------- fused setup + scatter (single block) ----------------
__global__ void __launch_bounds__(256) setup_scatter_kernel() {
    __shared__ int scnt[NEXP];
    __shared__ int soff[NEXP];
    __shared__ int sfill[NEXP];
    int tid = threadIdx.x;

    if (tid < NEXP) { scnt[tid] = 0; sfill[tid] = 0; }
    for (int i = tid; i < PADMAX; i += 256) g_perm_tok[i] = -1;
    if (tid < MAX_TILES) g_tile_e[tid] = -1;
    __syncthreads();

    for (int i = tid; i < TOKS*2; i += 256)
        atomicAdd(&scnt[g_top_i[i]], 1);
    __syncthreads();

    if (tid == 0) {
        int running = 0;
        for (int e = 0; e < NEXP; e++) {
            soff[e] = running;
            int nt = (scnt[e] + BM - 1) / BM;
            int t0 = running / BM;
            for (int t = 0; t < nt; t++) g_tile_e[t0 + t] = e;
            running += nt * BM;
        }
    }
    __syncthreads();

    for (int i = tid; i < TOKS*2; i += 256) {
        int e = g_top_i[i];
        int pos = atomicAdd(&sfill[e], 1);
        int gp = soff[e] + pos;
        g_perm_tok[gp] = i >> 1;
        g_apos[i] = gp;
    }
}

// ---------------- launcher ----------------
extern "C" void kernel_launch(void* const* d_in, const int* in_sizes, int n_in,
                              void* d_out, int out_size)
{
    const float* x      = (const float*)d_in[0];
    const float* ln_g   = (const float*)d_in[1];
    const float* ln_b   = (const float*)d_in[2];
    const float* rw     = (const float*)d_in[3];
    const float* rb     = (const float*)d_in[4];
    const float* ew1    = (const float*)d_in[5];
    const float* eb1    = (const float*)d_in[6];
    const float* ew2    = (const float*)d_in[7];
    const float* eb2    = (const float*)d_in[8];
    const float* sw1    = (const float*)d_in[9];
    const float* sb1    = (const float*)d_in[10];
    const float* sw2    = (const float*)d_in[11];
    const float* sb2    = (const float*)d_in[12];
    const float* ffln_g = (const float*)d_in[13];
    const float* ffln_b = (const float*)d_in[14];
    const float* ffw1   = (const float*)d_in[15];
    const float* ffb1   = (const float*)d_in[16];
    const float* ffw2   = (const float*)d_in[17];
    const float* ffb2   = (const float*)d_in[18];
    float* out = (float*)d_out;

    void* p;
    cudaGetSymbolAddress(&p, g_h);     __half* ph     = (__half*)p;
    cudaGetSymbolAddress(&p, g_mix);   float*  pmix   = (float*)p;
    cudaGetSymbolAddress(&p, g_fh);    __half* pfh    = (__half*)p;
    cudaGetSymbolAddress(&p, g_sact);  __half* psact  = (__half*)p;
    cudaGetSymbolAddress(&p, g_ffact); __half* pffact = (__half*)p;
    cudaGetSymbolAddress(&p, g_act1);  __half* pact1  = (__half*)p;
    cudaGetSymbolAddress(&p, g_y);     float*  py     = (float*)p;
    cudaGetSymbolAddress(&p, g_ew1h);  __half* pew1h  = (__half*)p;
    cudaGetSymbolAddress(&p, g_ew2h);  __half* pew2h  = (__half*)p;
    cudaGetSymbolAddress(&p, g_sw1h);  __half* psw1h  = (__half*)p;
    cudaGetSymbolAddress(&p, g_sw2h);  __half* psw2h  = (__half*)p;
    cudaGetSymbolAddress(&p, g_ffw1h); __half* pffw1h = (__half*)p;
    cudaGetSymbolAddress(&p, g_ffw2h); __half* pffw2h = (__half*)p;

    cudaFuncSetAttribute(g1_kernel,  cudaFuncAttributeMaxDynamicSharedMemorySize, SMEM_TOTAL);
    cudaFuncSetAttribute(g2_kernel,  cudaFuncAttributeMaxDynamicSharedMemorySize, SMEM_TOTAL);
    cudaFuncSetAttribute(ff1_kernel, cudaFuncAttributeMaxDynamicSharedMemorySize, SMEM_TOTAL);
    cudaFuncSetAttribute(ff2_kernel, cudaFuncAttributeMaxDynamicSharedMemorySize, SMEM_TOTAL);

    // 1. fused wide weight conversion + input LN + router (one launch)
    pre_kernel<<<PRE_BLOCKS, 256>>>(
        ew1, ew2, sw1, sw2, ffw1, ffw2,
        pew1h, pew2h, psw1h, psw2h, pffw1h, pffw2h,
        x, ln_g, ln_b, rw, rb, ph);
    // 2. counts + offsets + tile map + scatter
    setup_scatter_kernel<<<1, 256>>>();
    // 3. merged GEMM1: expert (gathered) + shared
    g1_kernel<<<G1_E_CTAS + G1_S_CTAS, 256, SMEM_TOTAL>>>(
        ph, pew1h, eb1, pact1, psw1h, sb1, psact);
    // 4. merged GEMM2: expert -> y, shared -> mix
    g2_kernel<<<G2_E_CTAS + G2_S_CTAS, 256, SMEM_TOTAL>>>(
        pact1, pew2h, eb2, py, psact, psw2h, sb2, pmix);
    // 5. combine(top-2) + final-FF LayerNorm
    ln2_kernel<<<TOKS, 128>>>(pmix, ffln_g, ffln_b, pfh);
    // 6. FF GEMM1 + SiLU
    ff1_kernel<<<512, 256, SMEM_TOTAL>>>(pfh, pffw1h, ffb1, pffact);
    // 7. FF GEMM2 + x + moe_out -> out
    ff2_kernel<<<128, 256, SMEM_TOTAL>>>(pffact, pffw2h, ffb2, out, x, pmix);
}